// round 3
// baseline (speedup 1.0000x reference)
#include <cuda_runtime.h>

#define T_STEPS 4096
#define BATCH   64
#define NSEQ    192   // 3 splits * 64 batch
#define FDIM    64

// Scratch: device globals (the allowed scratch mechanism)
// g_Z: pre-scaled (x@W + b)/2, layout [row r = (b*T+t)*3+s][j = gate*3+u], 12 floats/row
__device__ float g_Z[(size_t)NSEQ * T_STEPS * 12];              // 37.7 MB
// g_H: hidden states, layout [(b*T+t)*9 + s*3 + u]
__device__ float g_H[(size_t)BATCH * T_STEPS * 9];              // 9.4 MB

__device__ __forceinline__ float tanh_fast(float x) {
    float r;
    asm("tanh.approx.f32 %0, %1;" : "=f"(r) : "f"(x));
    return r;
}

// ---------------------------------------------------------------------------
// Kernel 1: Z[r][j] = 0.5 * ( x_row[r] @ W[:,j] + b[j] ),  r = (b*T+t)*3+s
// Stage 128 rows (32KB) of x through smem so global loads are coalesced.
// Each thread computes one row (64-dim dot x 12 outputs).
// ---------------------------------------------------------------------------
#define K1_ROWS 128
__global__ __launch_bounds__(K1_ROWS) void k1_gemm(const float* __restrict__ x,
                                                   const float* __restrict__ W,
                                                   const float* __restrict__ bias) {
    __shared__ float4 xs[K1_ROWS * 17];   // 128 rows x 16 float4, stride 17 (pad)
    __shared__ float4 Ws4[FDIM * 3];      // W pre-scaled by 0.5, [k][j/4]
    __shared__ float  bs[12];

    int tid = threadIdx.x;

    // stage W (scaled) and bias (scaled)
    for (int i = tid; i < FDIM * 3; i += K1_ROWS) {
        const float* wrow = W + i * 4;
        float4 v; v.x = 0.5f * wrow[0]; v.y = 0.5f * wrow[1];
        v.z = 0.5f * wrow[2]; v.w = 0.5f * wrow[3];
        Ws4[i] = v;
    }
    if (tid < 12) bs[tid] = 0.5f * bias[tid];

    // stage 128 rows of x, fully coalesced
    const float4* xg = (const float4*)x + (size_t)blockIdx.x * K1_ROWS * 16;
#pragma unroll
    for (int i = 0; i < 16; i++) {
        int f = i * K1_ROWS + tid;
        int row = f >> 4, c = f & 15;
        xs[row * 17 + c] = xg[f];
    }
    __syncthreads();

    float acc[12];
#pragma unroll
    for (int j = 0; j < 12; j++) acc[j] = bs[j];

#pragma unroll
    for (int k = 0; k < 16; k++) {
        float4 xv = xs[tid * 17 + k];
        float4 w0, w1, w2;
#pragma unroll
        for (int m = 0; m < 4; m++) {
            w0 = Ws4[(4 * k + m) * 3 + 0];
            w1 = Ws4[(4 * k + m) * 3 + 1];
            w2 = Ws4[(4 * k + m) * 3 + 2];
            float xm = (m == 0) ? xv.x : (m == 1) ? xv.y : (m == 2) ? xv.z : xv.w;
            acc[0] = fmaf(xm, w0.x, acc[0]);  acc[1]  = fmaf(xm, w0.y, acc[1]);
            acc[2] = fmaf(xm, w0.z, acc[2]);  acc[3]  = fmaf(xm, w0.w, acc[3]);
            acc[4] = fmaf(xm, w1.x, acc[4]);  acc[5]  = fmaf(xm, w1.y, acc[5]);
            acc[6] = fmaf(xm, w1.z, acc[6]);  acc[7]  = fmaf(xm, w1.w, acc[7]);
            acc[8] = fmaf(xm, w2.x, acc[8]);  acc[9]  = fmaf(xm, w2.y, acc[9]);
            acc[10] = fmaf(xm, w2.z, acc[10]); acc[11] = fmaf(xm, w2.w, acc[11]);
        }
    }

    size_t R = (size_t)blockIdx.x * K1_ROWS + tid;
    float4* zp = (float4*)g_Z + R * 3;
    zp[0] = make_float4(acc[0], acc[1], acc[2], acc[3]);
    zp[1] = make_float4(acc[4], acc[5], acc[6], acc[7]);
    zp[2] = make_float4(acc[8], acc[9], acc[10], acc[11]);
}

// ---------------------------------------------------------------------------
// Kernel 2: recurrence. ONE THREAD PER SEQUENCE (all 3 units) — no shfl on the
// critical path. 192 threads = 6 warps = 6 blocks. State d = c/2, z pre-scaled
// by 0.5, U scaled by 0.5, so every sigmoid folds to a single tanh.
// Bound: 15 MUFU/step * rt8 = ~120 cyc/step.
// ---------------------------------------------------------------------------
__global__ __launch_bounds__(32, 1) void k2_lstm(const float* __restrict__ U) {
    int g = blockIdx.x * 32 + threadIdx.x;   // 0..191
    int b = g / 3;
    int s = g - 3 * b;

    // Uh[k][j] = 0.5 * U[k][j],  j = gate*3+u
    float Uh[3][12];
#pragma unroll
    for (int k = 0; k < 3; k++)
#pragma unroll
        for (int j = 0; j < 12; j++) Uh[k][j] = 0.5f * U[k * 12 + j];

    // Z rows for this sequence: r(t) = 3*b*T + 3*t + s  (float4 idx = 3*r)
    const float4* zp = (const float4*)g_Z + ((size_t)9 * b * T_STEPS + 3 * s);
    float* hp = g_H + ((size_t)b * T_STEPS) * 9 + s * 3;

    const int PD = 4;
    float4 ring[PD][3];
#pragma unroll
    for (int p = 0; p < PD; p++) {
        ring[p][0] = zp[9 * p + 0];
        ring[p][1] = zp[9 * p + 1];
        ring[p][2] = zp[9 * p + 2];
    }

    float h0 = 0.f, h1 = 0.f, h2 = 0.f;
    float d0 = 0.f, d1 = 0.f, d2 = 0.f;

    for (int t0 = 0; t0 < T_STEPS; t0 += PD) {
#pragma unroll
        for (int q = 0; q < PD; q++) {
            int t = t0 + q;
            float4 A = ring[q][0];   // i0 i1 i2 f0
            float4 Bv = ring[q][1];  // f1 f2 g0 g1
            float4 C = ring[q][2];   // g2 o0 o1 o2

            int tp = (t + PD) & (T_STEPS - 1);   // wrap-safe prefetch
            ring[q][0] = zp[9 * tp + 0];
            ring[q][1] = zp[9 * tp + 1];
            ring[q][2] = zp[9 * tp + 2];

            float z[12] = {A.x, A.y, A.z, A.w, Bv.x, Bv.y, Bv.z, Bv.w,
                           C.x, C.y, C.z, C.w};
            float pre[12];
#pragma unroll
            for (int j = 0; j < 12; j++)
                pre[j] = fmaf(h2, Uh[2][j],
                         fmaf(h1, Uh[1][j],
                         fmaf(h0, Uh[0][j], z[j])));

            // unit 0
            {
                float ti = tanh_fast(pre[0]);
                float tf = tanh_fast(pre[3]);
                float tg = tanh_fast(pre[6]);
                float to = tanh_fast(pre[9]);
                float ih = fmaf(ti, 0.25f, 0.25f);
                float gf = fmaf(tg, 0.50f, 0.50f);
                float ff = fmaf(tf, 0.50f, 0.50f);
                float oh = fmaf(to, 0.25f, 0.25f);
                d0 = fmaf(ff, d0, ih * gf);
                h0 = fmaf(oh, tanh_fast(d0), oh);
            }
            // unit 1
            {
                float ti = tanh_fast(pre[1]);
                float tf = tanh_fast(pre[4]);
                float tg = tanh_fast(pre[7]);
                float to = tanh_fast(pre[10]);
                float ih = fmaf(ti, 0.25f, 0.25f);
                float gf = fmaf(tg, 0.50f, 0.50f);
                float ff = fmaf(tf, 0.50f, 0.50f);
                float oh = fmaf(to, 0.25f, 0.25f);
                d1 = fmaf(ff, d1, ih * gf);
                h1 = fmaf(oh, tanh_fast(d1), oh);
            }
            // unit 2
            {
                float ti = tanh_fast(pre[2]);
                float tf = tanh_fast(pre[5]);
                float tg = tanh_fast(pre[8]);
                float to = tanh_fast(pre[11]);
                float ih = fmaf(ti, 0.25f, 0.25f);
                float gf = fmaf(tg, 0.50f, 0.50f);
                float ff = fmaf(tf, 0.50f, 0.50f);
                float oh = fmaf(to, 0.25f, 0.25f);
                d2 = fmaf(ff, d2, ih * gf);
                h2 = fmaf(oh, tanh_fast(d2), oh);
            }

            float* hw = hp + (size_t)t * 9;
            hw[0] = h0; hw[1] = h1; hw[2] = h2;
        }
    }
}

// ---------------------------------------------------------------------------
// Kernel 3: out[b,t,:] = sigmoid( h9[b,t,:] @ Wd + bd ); h9 contiguous 36B/thread.
// ---------------------------------------------------------------------------
__global__ __launch_bounds__(256) void k3_dense(const float* __restrict__ Wd,
                                                const float* __restrict__ bd,
                                                float* __restrict__ out) {
    __shared__ float Wds[36];
    __shared__ float bds[4];
    int tid = threadIdx.x;
    if (tid < 36) Wds[tid] = Wd[tid];
    if (tid < 4)  bds[tid] = bd[tid];
    __syncthreads();

    int gid = blockIdx.x * blockDim.x + tid;  // gid = b*T + t
    const float* hpp = g_H + (size_t)gid * 9;

    float a0 = bds[0], a1 = bds[1], a2 = bds[2], a3 = bds[3];
#pragma unroll
    for (int m = 0; m < 9; m++) {
        float hv = hpp[m];
        a0 = fmaf(hv, Wds[m * 4 + 0], a0);
        a1 = fmaf(hv, Wds[m * 4 + 1], a1);
        a2 = fmaf(hv, Wds[m * 4 + 2], a2);
        a3 = fmaf(hv, Wds[m * 4 + 3], a3);
    }
    float4 r;
    r.x = 1.0f / (1.0f + __expf(-a0));
    r.y = 1.0f / (1.0f + __expf(-a1));
    r.z = 1.0f / (1.0f + __expf(-a2));
    r.w = 1.0f / (1.0f + __expf(-a3));
    ((float4*)out)[gid] = r;
}

extern "C" void kernel_launch(void* const* d_in, const int* in_sizes, int n_in,
                              void* d_out, int out_size) {
    const float* x    = (const float*)d_in[0];
    const float* W    = (const float*)d_in[1];
    const float* U    = (const float*)d_in[2];
    const float* bias = (const float*)d_in[3];
    const float* Wd   = (const float*)d_in[4];
    const float* bd   = (const float*)d_in[5];
    float* out = (float*)d_out;

    k1_gemm<<<6144, K1_ROWS>>>(x, W, bias);   // 786432 rows, 128/block
    k2_lstm<<<6, 32>>>(U);                    // 192 sequences, 1 thread each
    k3_dense<<<1024, 256>>>(Wd, bd, out);     // 262144 (b,t) pairs

    (void)in_sizes; (void)n_in; (void)out_size;
}

// round 4
// speedup vs baseline: 1.3812x; 1.3812x over previous
#include <cuda_runtime.h>

#define T_STEPS 4096
#define BATCH   64
#define NSEQ    192   // 3 splits * 64 batch
#define FDIM    64

// Scratch: device globals (the allowed scratch mechanism)
// g_Z: pre-scaled (x@W + b)/2. Layout: float4 Z4[t][j4][g], t<4096, j4<3, g<192
//      (g = 3*b + s). Coalesced across g for the recurrence warp.
__device__ float g_Z[(size_t)NSEQ * T_STEPS * 12];              // 37.7 MB
// g_H: hidden states. Layout: float H[t][g][3]  (g = 3*b + s)
__device__ float g_H[(size_t)BATCH * T_STEPS * 9];              // 9.4 MB

__device__ __forceinline__ float tanh_fast(float x) {
    float r;
    asm("tanh.approx.f32 %0, %1;" : "=f"(r) : "f"(x));
    return r;
}

// ---------------------------------------------------------------------------
// Kernel 1: for row r = (b*T+t)*3+s compute 12 preactivations
//   acc[j] = 0.5*(x_row[r] @ W[:,j] + b[j]),  j = gate*3+u
// and scatter into transposed Z layout Z4[t][j4][3b+s].
// x rows staged through smem so global loads are coalesced.
// ---------------------------------------------------------------------------
#define K1_ROWS 128
__global__ __launch_bounds__(K1_ROWS) void k1_gemm(const float* __restrict__ x,
                                                   const float* __restrict__ W,
                                                   const float* __restrict__ bias) {
    __shared__ float4 xs[K1_ROWS * 17];   // 128 rows x 16 float4, stride 17 (pad)
    __shared__ float4 Ws4[FDIM * 3];      // W pre-scaled by 0.5, [k][j/4]
    __shared__ float  bs[12];

    int tid = threadIdx.x;

    for (int i = tid; i < FDIM * 3; i += K1_ROWS) {
        const float* wrow = W + i * 4;
        float4 v; v.x = 0.5f * wrow[0]; v.y = 0.5f * wrow[1];
        v.z = 0.5f * wrow[2]; v.w = 0.5f * wrow[3];
        Ws4[i] = v;
    }
    if (tid < 12) bs[tid] = 0.5f * bias[tid];

    const float4* xg = (const float4*)x + (size_t)blockIdx.x * K1_ROWS * 16;
#pragma unroll
    for (int i = 0; i < 16; i++) {
        int f = i * K1_ROWS + tid;
        int row = f >> 4, c = f & 15;
        xs[row * 17 + c] = xg[f];
    }
    __syncthreads();

    float acc[12];
#pragma unroll
    for (int j = 0; j < 12; j++) acc[j] = bs[j];

#pragma unroll
    for (int k = 0; k < 16; k++) {
        float4 xv = xs[tid * 17 + k];
        float4 w0, w1, w2;
#pragma unroll
        for (int m = 0; m < 4; m++) {
            w0 = Ws4[(4 * k + m) * 3 + 0];
            w1 = Ws4[(4 * k + m) * 3 + 1];
            w2 = Ws4[(4 * k + m) * 3 + 2];
            float xm = (m == 0) ? xv.x : (m == 1) ? xv.y : (m == 2) ? xv.z : xv.w;
            acc[0] = fmaf(xm, w0.x, acc[0]);  acc[1]  = fmaf(xm, w0.y, acc[1]);
            acc[2] = fmaf(xm, w0.z, acc[2]);  acc[3]  = fmaf(xm, w0.w, acc[3]);
            acc[4] = fmaf(xm, w1.x, acc[4]);  acc[5]  = fmaf(xm, w1.y, acc[5]);
            acc[6] = fmaf(xm, w1.z, acc[6]);  acc[7]  = fmaf(xm, w1.w, acc[7]);
            acc[8] = fmaf(xm, w2.x, acc[8]);  acc[9]  = fmaf(xm, w2.y, acc[9]);
            acc[10] = fmaf(xm, w2.z, acc[10]); acc[11] = fmaf(xm, w2.w, acc[11]);
        }
    }

    // r = (b*T+t)*3+s  ->  g = 3b+s, scatter to Z4[t][j4][g]
    size_t r = (size_t)blockIdx.x * K1_ROWS + tid;
    int s = (int)(r % 3);
    size_t rem = r / 3;
    int t  = (int)(rem & (T_STEPS - 1));
    int b  = (int)(rem >> 12);
    int g  = 3 * b + s;

    float4* z4 = (float4*)g_Z;
    size_t base = (size_t)t * 3 * NSEQ + g;
    z4[base]            = make_float4(acc[0], acc[1], acc[2],  acc[3]);
    z4[base + NSEQ]     = make_float4(acc[4], acc[5], acc[6],  acc[7]);
    z4[base + 2 * NSEQ] = make_float4(acc[8], acc[9], acc[10], acc[11]);
}

// ---------------------------------------------------------------------------
// Kernel 2: recurrence. One thread per sequence (all 3 units) — no shfl on
// the critical path. 192 threads = 6 single-warp blocks on 6 SMs.
// Coalesced loads: 3 x LDG.128 x 512B contiguous per warp-step (12 wavefronts).
// State d = c/2, z and U pre-scaled by 0.5 -> every sigmoid is one tanh.
// Throughput bound: 15 MUFU/step * rt8 = ~120 cyc/step.
// ---------------------------------------------------------------------------
__global__ __launch_bounds__(32, 1) void k2_lstm(const float* __restrict__ U) {
    int g = blockIdx.x * 32 + threadIdx.x;   // 0..191

    float Uh[3][12];
#pragma unroll
    for (int k = 0; k < 3; k++)
#pragma unroll
        for (int j = 0; j < 12; j++) Uh[k][j] = 0.5f * U[k * 12 + j];

    const float4* zb = (const float4*)g_Z;       // [t][3][192]
    float* hw = g_H + (size_t)g * 3;             // [t][192][3]

    const int PD = 6;
    float4 ring[PD][3];
#pragma unroll
    for (int p = 0; p < PD; p++) {
        size_t idx = (size_t)p * 3 * NSEQ + g;
        ring[p][0] = zb[idx];
        ring[p][1] = zb[idx + NSEQ];
        ring[p][2] = zb[idx + 2 * NSEQ];
    }

    float h0 = 0.f, h1 = 0.f, h2 = 0.f;
    float d0 = 0.f, d1 = 0.f, d2 = 0.f;

    for (int t0 = 0; t0 < T_STEPS; t0 += PD) {
#pragma unroll
        for (int q = 0; q < PD; q++) {
            int t = t0 + q;
            float4 A  = ring[q][0];   // i0 i1 i2 f0
            float4 Bv = ring[q][1];   // f1 f2 g0 g1
            float4 C  = ring[q][2];   // g2 o0 o1 o2

            // prefetch step t+PD into this slot (wrap-masked; wrapped data
            // is never consumed)
            int tp = (t + PD) & (T_STEPS - 1);
            size_t pidx = (size_t)tp * 3 * NSEQ + g;
            ring[q][0] = zb[pidx];
            ring[q][1] = zb[pidx + NSEQ];
            ring[q][2] = zb[pidx + 2 * NSEQ];

            float z[12] = {A.x, A.y, A.z, A.w, Bv.x, Bv.y, Bv.z, Bv.w,
                           C.x, C.y, C.z, C.w};
            float pre[12];
#pragma unroll
            for (int j = 0; j < 12; j++)
                pre[j] = fmaf(h2, Uh[2][j],
                         fmaf(h1, Uh[1][j],
                         fmaf(h0, Uh[0][j], z[j])));

            // unit 0
            {
                float ti = tanh_fast(pre[0]);
                float tf = tanh_fast(pre[3]);
                float tg = tanh_fast(pre[6]);
                float to = tanh_fast(pre[9]);
                float ih = fmaf(ti, 0.25f, 0.25f);
                float gf = fmaf(tg, 0.50f, 0.50f);
                float ff = fmaf(tf, 0.50f, 0.50f);
                float oh = fmaf(to, 0.25f, 0.25f);
                d0 = fmaf(ff, d0, ih * gf);
                h0 = fmaf(oh, tanh_fast(d0), oh);
            }
            // unit 1
            {
                float ti = tanh_fast(pre[1]);
                float tf = tanh_fast(pre[4]);
                float tg = tanh_fast(pre[7]);
                float to = tanh_fast(pre[10]);
                float ih = fmaf(ti, 0.25f, 0.25f);
                float gf = fmaf(tg, 0.50f, 0.50f);
                float ff = fmaf(tf, 0.50f, 0.50f);
                float oh = fmaf(to, 0.25f, 0.25f);
                d1 = fmaf(ff, d1, ih * gf);
                h1 = fmaf(oh, tanh_fast(d1), oh);
            }
            // unit 2
            {
                float ti = tanh_fast(pre[2]);
                float tf = tanh_fast(pre[5]);
                float tg = tanh_fast(pre[8]);
                float to = tanh_fast(pre[11]);
                float ih = fmaf(ti, 0.25f, 0.25f);
                float gf = fmaf(tg, 0.50f, 0.50f);
                float ff = fmaf(tf, 0.50f, 0.50f);
                float oh = fmaf(to, 0.25f, 0.25f);
                d2 = fmaf(ff, d2, ih * gf);
                h2 = fmaf(oh, tanh_fast(d2), oh);
            }

            // coalesced: warp writes 384B contiguous
            float* hp = hw + (size_t)t * (NSEQ * 3);
            hp[0] = h0; hp[1] = h1; hp[2] = h2;
        }
    }
}

// ---------------------------------------------------------------------------
// Kernel 3: out[b,t,:] = sigmoid( h9[b,t,:] @ Wd + bd )
// gid = t*64 + b  ->  H reads are coalesced (9 contiguous floats per thread,
// consecutive threads = consecutive b).
// ---------------------------------------------------------------------------
__global__ __launch_bounds__(256) void k3_dense(const float* __restrict__ Wd,
                                                const float* __restrict__ bd,
                                                float* __restrict__ out) {
    __shared__ float Wds[36];
    __shared__ float bds[4];
    int tid = threadIdx.x;
    if (tid < 36) Wds[tid] = Wd[tid];
    if (tid < 4)  bds[tid] = bd[tid];
    __syncthreads();

    int gid = blockIdx.x * 256 + tid;     // gid = t*64 + b
    int b = gid & 63;
    int t = gid >> 6;

    const float* hpp = g_H + (size_t)t * (NSEQ * 3) + 9 * b;  // h[s*3+u], s-major

    float a0 = bds[0], a1 = bds[1], a2 = bds[2], a3 = bds[3];
#pragma unroll
    for (int m = 0; m < 9; m++) {
        float hv = hpp[m];
        a0 = fmaf(hv, Wds[m * 4 + 0], a0);
        a1 = fmaf(hv, Wds[m * 4 + 1], a1);
        a2 = fmaf(hv, Wds[m * 4 + 2], a2);
        a3 = fmaf(hv, Wds[m * 4 + 3], a3);
    }
    float4 r;
    r.x = 1.0f / (1.0f + __expf(-a0));
    r.y = 1.0f / (1.0f + __expf(-a1));
    r.z = 1.0f / (1.0f + __expf(-a2));
    r.w = 1.0f / (1.0f + __expf(-a3));
    ((float4*)out)[(size_t)b * T_STEPS + t] = r;
}

extern "C" void kernel_launch(void* const* d_in, const int* in_sizes, int n_in,
                              void* d_out, int out_size) {
    const float* x    = (const float*)d_in[0];
    const float* W    = (const float*)d_in[1];
    const float* U    = (const float*)d_in[2];
    const float* bias = (const float*)d_in[3];
    const float* Wd   = (const float*)d_in[4];
    const float* bd   = (const float*)d_in[5];
    float* out = (float*)d_out;

    k1_gemm<<<6144, K1_ROWS>>>(x, W, bias);   // 786432 rows, 128/block
    k2_lstm<<<6, 32>>>(U);                    // 192 sequences, 1 thread each
    k3_dense<<<1024, 256>>>(Wd, bd, out);     // 262144 (b,t) pairs

    (void)in_sizes; (void)n_in; (void)out_size;
}

// round 6
// speedup vs baseline: 1.9880x; 1.4394x over previous
#include <cuda_runtime.h>

#define T_STEPS 4096
#define BATCH   64
#define NSEQ    192    // 3 splits * 64 batch, seq = 3*b + s
#define FDIM    64
#define NWARP   20     // k2 warps, 10 sequences each (30 active lanes)
#define PD      8      // k2 prefetch depth

// ---------------------------------------------------------------------------
// Scratch (device globals are the allowed scratch mechanism)
// g_Z4[t][w][lane]: float4 (zi,zf,zg,zo)/2 for (seq = w*10 + lane/3, unit = lane%3)
//   padded by PD steps so the prefetch pointer never wraps.
// g_H[t][b][s*3+u]: hidden states, 576 floats per t; warp w writes floats
//   [t*576 + 30w, t*576 + 30w + 30) each step (fully coalesced).
// ---------------------------------------------------------------------------
__device__ float4 g_Z4[(size_t)(T_STEPS + PD) * NWARP * 32];    // ~42 MB
__device__ float  g_H[(size_t)T_STEPS * BATCH * 9];             // 9.4 MB

__device__ __forceinline__ float tanh_fast(float x) {
    float r;
    asm("tanh.approx.f32 %0, %1;" : "=f"(r) : "f"(x));
    return r;
}

// ---------------------------------------------------------------------------
// Kernel 1: row r = (b*T+t)*3+s -> 12 preactivations 0.5*(x_row @ W + b),
// scattered to g_Z4[t][w][3*(g%10)+u], g = 3b+s, w = g/10.
// ---------------------------------------------------------------------------
#define K1_ROWS 128
__global__ __launch_bounds__(K1_ROWS) void k1_gemm(const float* __restrict__ x,
                                                   const float* __restrict__ W,
                                                   const float* __restrict__ bias) {
    __shared__ float4 xs[K1_ROWS * 17];   // 128 rows x 16 float4, stride 17 (pad)
    __shared__ float4 Ws4[FDIM * 3];      // W pre-scaled by 0.5
    __shared__ float  bs[12];

    int tid = threadIdx.x;

    for (int i = tid; i < FDIM * 3; i += K1_ROWS) {
        const float* wrow = W + i * 4;
        float4 v; v.x = 0.5f * wrow[0]; v.y = 0.5f * wrow[1];
        v.z = 0.5f * wrow[2]; v.w = 0.5f * wrow[3];
        Ws4[i] = v;
    }
    if (tid < 12) bs[tid] = 0.5f * bias[tid];

    const float4* xg = (const float4*)x + (size_t)blockIdx.x * K1_ROWS * 16;
#pragma unroll
    for (int i = 0; i < 16; i++) {
        int f = i * K1_ROWS + tid;
        int row = f >> 4, c = f & 15;
        xs[row * 17 + c] = xg[f];
    }
    __syncthreads();

    float acc[12];
#pragma unroll
    for (int j = 0; j < 12; j++) acc[j] = bs[j];

#pragma unroll
    for (int k = 0; k < 16; k++) {
        float4 xv = xs[tid * 17 + k];
        float4 w0, w1, w2;
#pragma unroll
        for (int m = 0; m < 4; m++) {
            w0 = Ws4[(4 * k + m) * 3 + 0];
            w1 = Ws4[(4 * k + m) * 3 + 1];
            w2 = Ws4[(4 * k + m) * 3 + 2];
            float xm = (m == 0) ? xv.x : (m == 1) ? xv.y : (m == 2) ? xv.z : xv.w;
            acc[0] = fmaf(xm, w0.x, acc[0]);  acc[1]  = fmaf(xm, w0.y, acc[1]);
            acc[2] = fmaf(xm, w0.z, acc[2]);  acc[3]  = fmaf(xm, w0.w, acc[3]);
            acc[4] = fmaf(xm, w1.x, acc[4]);  acc[5]  = fmaf(xm, w1.y, acc[5]);
            acc[6] = fmaf(xm, w1.z, acc[6]);  acc[7]  = fmaf(xm, w1.w, acc[7]);
            acc[8] = fmaf(xm, w2.x, acc[8]);  acc[9]  = fmaf(xm, w2.y, acc[9]);
            acc[10] = fmaf(xm, w2.z, acc[10]); acc[11] = fmaf(xm, w2.w, acc[11]);
        }
    }

    size_t r = (size_t)blockIdx.x * K1_ROWS + tid;
    int s = (int)(r % 3);
    size_t rem = r / 3;
    int t  = (int)(rem & (T_STEPS - 1));
    int b  = (int)(rem >> 12);
    int g  = 3 * b + s;
    int w  = g / 10;
    int l3 = 3 * (g - 10 * w);

    float4* zp = g_Z4 + ((size_t)t * NWARP + w) * 32 + l3;
    // acc[j], j = gate*3+u:  per unit u the float4 is (i,f,g,o)
    zp[0] = make_float4(acc[0], acc[3], acc[6], acc[9]);
    zp[1] = make_float4(acc[1], acc[4], acc[7], acc[10]);
    zp[2] = make_float4(acc[2], acc[5], acc[8], acc[11]);
}

// ---------------------------------------------------------------------------
// Kernel 2: recurrence. lane = (group, unit); 10 sequences per warp.
// 5 tanh + 2 shfl + ~20 FMA + 1 LDG + 1 STG per step; all inner offsets are
// immediates (Z padded so the PD-ahead prefetch pointer never wraps).
// Guard: warp 19 only has sequences 190,191 (grp<2) — phantom lanes compute
// but NEVER store (R5 bug: their stores aliased into timestep t+1's H).
// ---------------------------------------------------------------------------
__global__ __launch_bounds__(32, 1) void k2_lstm(const float* __restrict__ U) {
    int lane = threadIdx.x;
    int grp  = lane / 3;
    int u    = lane - 3 * grp;
    int w    = blockIdx.x;
    bool active = (lane < 30) && (w * 10 + grp < NSEQ);

    int ua = u + 1; if (ua >= 3) ua -= 3;
    int ub = u + 2; if (ub >= 3) ub -= 3;
    int la = grp * 3 + ua; if (la > 31) la = 31;
    int lb = grp * 3 + ub; if (lb > 31) lb = 31;

    // 0.5-scaled recurrent weights for this lane's unit column
    float Uo[4], Ua[4], Ub[4];
#pragma unroll
    for (int g = 0; g < 4; g++) {
        Uo[g] = 0.5f * U[u  * 12 + g * 3 + u];
        Ua[g] = 0.5f * U[ua * 12 + g * 3 + u];
        Ub[g] = 0.5f * U[ub * 12 + g * 3 + u];
    }

    const float4* zp = g_Z4 + (size_t)w * 32 + lane;   // step stride NWARP*32
    float* hp = g_H + 30 * w + lane;                   // step stride 576

    float4 ring[PD];
#pragma unroll
    for (int p = 0; p < PD; p++) ring[p] = zp[(size_t)p * (NWARP * 32)];
    const float4* zpp = zp + (size_t)PD * (NWARP * 32);  // prefetch ptr, never wraps

    float h = 0.0f, d = 0.0f;

    for (int t0 = 0; t0 < T_STEPS; t0 += PD) {
#pragma unroll
        for (int q = 0; q < PD; q++) {
            float4 zv = ring[q];
            ring[q] = zpp[(size_t)q * (NWARP * 32)];

            float ha = __shfl_sync(0xffffffffu, h, la);
            float hb = __shfl_sync(0xffffffffu, h, lb);

            float p0 = fmaf(h, Uo[0], zv.x);
            float p1 = fmaf(h, Uo[1], zv.y);
            float p2 = fmaf(h, Uo[2], zv.z);
            float p3 = fmaf(h, Uo[3], zv.w);
            float q0 = fmaf(ha, Ua[0], p0);
            float q1 = fmaf(ha, Ua[1], p1);
            float q2 = fmaf(ha, Ua[2], p2);
            float q3 = fmaf(ha, Ua[3], p3);
            float pre0 = fmaf(hb, Ub[0], q0);
            float pre1 = fmaf(hb, Ub[1], q1);
            float pre2 = fmaf(hb, Ub[2], q2);
            float pre3 = fmaf(hb, Ub[3], q3);

            float ti = tanh_fast(pre0);
            float tf = tanh_fast(pre1);
            float tg = tanh_fast(pre2);
            float to = tanh_fast(pre3);

            float ih = fmaf(ti, 0.25f, 0.25f);   // sigma(zi)/2
            float ff = fmaf(tf, 0.50f, 0.50f);   // sigma(zf)
            float gf = fmaf(tg, 0.50f, 0.50f);   // sigma(zg)
            float oh = fmaf(to, 0.25f, 0.25f);   // sigma(zo)/2

            d = fmaf(ff, d, ih * gf);            // d = c_new/2
            h = fmaf(oh, tanh_fast(d), oh);      // sigma(zo)*sigma(c_new)

            if (active) hp[(size_t)(t0 + q) * 576] = h;
        }
        zpp += (size_t)PD * (NWARP * 32);
    }
}

// ---------------------------------------------------------------------------
// Kernel 3: out[b,t,:] = sigmoid( h9 @ Wd + bd ), h9 = g_H[t*576 + 9b + m],
// m = s*3+u already in Wd row order. gid = t*64 + b -> coalesced H reads.
// ---------------------------------------------------------------------------
__global__ __launch_bounds__(256) void k3_dense(const float* __restrict__ Wd,
                                                const float* __restrict__ bd,
                                                float* __restrict__ out) {
    __shared__ float Wds[36];
    __shared__ float bds[4];
    int tid = threadIdx.x;
    if (tid < 36) Wds[tid] = Wd[tid];
    if (tid < 4)  bds[tid] = bd[tid];
    __syncthreads();

    int gid = blockIdx.x * 256 + tid;     // gid = t*64 + b
    int b = gid & 63;
    int t = gid >> 6;

    const float* hpp = g_H + (size_t)t * 576 + 9 * b;

    float a0 = bds[0], a1 = bds[1], a2 = bds[2], a3 = bds[3];
#pragma unroll
    for (int m = 0; m < 9; m++) {
        float hv = hpp[m];
        a0 = fmaf(hv, Wds[m * 4 + 0], a0);
        a1 = fmaf(hv, Wds[m * 4 + 1], a1);
        a2 = fmaf(hv, Wds[m * 4 + 2], a2);
        a3 = fmaf(hv, Wds[m * 4 + 3], a3);
    }
    float4 r;
    r.x = 1.0f / (1.0f + __expf(-a0));
    r.y = 1.0f / (1.0f + __expf(-a1));
    r.z = 1.0f / (1.0f + __expf(-a2));
    r.w = 1.0f / (1.0f + __expf(-a3));
    ((float4*)out)[(size_t)b * T_STEPS + t] = r;
}

extern "C" void kernel_launch(void* const* d_in, const int* in_sizes, int n_in,
                              void* d_out, int out_size) {
    const float* x    = (const float*)d_in[0];
    const float* W    = (const float*)d_in[1];
    const float* U    = (const float*)d_in[2];
    const float* bias = (const float*)d_in[3];
    const float* Wd   = (const float*)d_in[4];
    const float* bd   = (const float*)d_in[5];
    float* out = (float*)d_out;

    k1_gemm<<<6144, K1_ROWS>>>(x, W, bias);
    k2_lstm<<<NWARP, 32>>>(U);
    k3_dense<<<1024, 256>>>(Wd, bd, out);

    (void)in_sizes; (void)n_in; (void)out_size;
}